// round 15
// baseline (speedup 1.0000x reference)
#include <cuda_runtime.h>
#include <cstdint>

// Problem constants
#define HB   4
#define HS   1024
#define HD   1024
#define HH   16
#define HDK  64
#define MTOT (HB*HS)          // 4096
#define NBH  (HB*HH)          // 64
#define OUT_ELEMS (MTOT*HD)   // 4194304

// Scratch (allocation-free device globals) — all tf32-converted fp32 bits
__device__ float g_X[3*MTOT*HD];     // cvt inputs q,k,v (A); slot0 reused for ctx
__device__ float g_W[4*HD*HD];       // W^T [n][k] (B)
__device__ float g_Q[NBH*HS*HDK];    // [bh][s][d] row-major, pre-scaled (A)
__device__ float g_K[NBH*HS*HDK];    // [bh][key][d] (B)
__device__ float g_VT[NBH*HDK*HS];   // [bh][d][s] (B) — written by V-proj epilogue

// ---------------------------------------------------------------------------
// helpers
// ---------------------------------------------------------------------------
__device__ __forceinline__ uint32_t smem_u32(const void* p) {
    uint32_t a;
    asm("{ .reg .u64 t; cvta.to.shared.u64 t, %1; cvt.u32.u64 %0, t; }"
        : "=r"(a) : "l"(p));
    return a;
}
__device__ __forceinline__ uint32_t cvt_tf32(float f) {
    uint32_t o;
    asm("cvt.rna.tf32.f32 %0, %1;" : "=r"(o) : "f"(f));
    return o;
}
__device__ __forceinline__ void ldmx4(uint32_t* r, uint32_t addr) {
    asm volatile("ldmatrix.sync.aligned.m8n8.x4.shared.b16 {%0,%1,%2,%3}, [%4];"
        : "=r"(r[0]), "=r"(r[1]), "=r"(r[2]), "=r"(r[3]) : "r"(addr));
}
__device__ __forceinline__ void mma_tf32(float* c, uint32_t a0, uint32_t a1,
                                         uint32_t a2, uint32_t a3,
                                         uint32_t b0, uint32_t b1) {
    asm volatile(
        "mma.sync.aligned.m16n8k8.row.col.f32.tf32.tf32.f32 "
        "{%0,%1,%2,%3}, {%4,%5,%6,%7}, {%8,%9}, {%0,%1,%2,%3};"
        : "+f"(c[0]), "+f"(c[1]), "+f"(c[2]), "+f"(c[3])
        : "r"(a0), "r"(a1), "r"(a2), "r"(a3), "r"(b0), "r"(b1));
}
#define CP16(dst, src) asm volatile("cp.async.cg.shared.global [%0], [%1], 16;" :: "r"(dst), "l"(src))
#define CP_COMMIT()    asm volatile("cp.async.commit_group;" ::: "memory")
#define CP_WAIT1()     asm volatile("cp.async.wait_group 1;" ::: "memory")
#define CP_WAIT0()     asm volatile("cp.async.wait_group 0;" ::: "memory")
#define BAR_PROD()     asm volatile("bar.sync 1, 256;" ::: "memory")

// ---------------------------------------------------------------------------
// q,k,v fp32 -> tf32-cvt fp32 into g_X, one launch
// ---------------------------------------------------------------------------
#define N4 (OUT_ELEMS/4)
__global__ __launch_bounds__(256)
void repackQKV_k(const float4* __restrict__ q, const float4* __restrict__ k,
                 const float4* __restrict__ v)
{
    int i = blockIdx.x * 256 + threadIdx.x;          // 0 .. 3*N4
    int z = i / N4, j = i - z * N4;
    const float4* src = (z == 0) ? q : (z == 1) ? k : v;
    float4 val = src[j];
    uint4 o;
    o.x = cvt_tf32(val.x); o.y = cvt_tf32(val.y);
    o.z = cvt_tf32(val.z); o.w = cvt_tf32(val.w);
    ((uint4*)(g_X + (size_t)z * OUT_ELEMS))[j] = o;
}

// ---------------------------------------------------------------------------
// All 4 weights: W[k][n] fp32 -> W^T [n][k] tf32-cvt
// ---------------------------------------------------------------------------
__global__ __launch_bounds__(256)
void wT4_k(const float* __restrict__ Wq, const float* __restrict__ Wk,
           const float* __restrict__ Wv, const float* __restrict__ Wo)
{
    __shared__ float t[32][33];
    const int z = blockIdx.z;
    const float* W = (z == 0) ? Wq : (z == 1) ? Wk : (z == 2) ? Wv : Wo;
    uint32_t* dst = (uint32_t*)(g_W + (size_t)z * HD * HD);
    int k0 = blockIdx.y * 32, n0 = blockIdx.x * 32;
    int tx = threadIdx.x, ty = threadIdx.y;   // (32, 8)
#pragma unroll
    for (int j = 0; j < 32; j += 8)
        t[ty + j][tx] = W[(size_t)(k0 + ty + j) * HD + n0 + tx];
    __syncthreads();
#pragma unroll
    for (int j = 0; j < 32; j += 8)
        dst[(size_t)(n0 + ty + j) * HD + k0 + tx] = cvt_tf32(t[tx][ty + j]);
}

// ---------------------------------------------------------------------------
// Dense tf32 GEMM (BM=256,BN=128,BK=32), cp.async 3-stage, ldmatrix frags.
// 512 threads, 16 warps = 4(m)x4(n) grid, warp tile 64x32.
// PROJ=true: blockIdx.z in {0,1,2} = Q/K/V (V writes g_VT transposed).
// PROJ=false: out = ctx @ Wo + bo, fp32 row-major.
// ---------------------------------------------------------------------------
#define GSTRB 144                    // 32 floats + 16B pad (stride ≡ 4 mod 32 words)
#define GA_BYTES (256*GSTRB)         // 36864
#define GB_BYTES (128*GSTRB)         // 18432
#define GSTG (GA_BYTES + GB_BYTES)   // 55296
#define GT_SMEM (3*GSTG)             // 165888

template<bool PROJ>
__global__ __launch_bounds__(512, 1)
void gemm5(const float* __restrict__ b0, const float* __restrict__ b1,
           const float* __restrict__ b2, float* __restrict__ outp)
{
    extern __shared__ char sm[];
    const uint32_t sb = smem_u32(sm);
    const int z = PROJ ? blockIdx.z : 3;
    const int tid = threadIdx.x;
    const int wid = tid >> 5, lane = tid & 31;
    const int wm = wid & 3, wn = wid >> 2;          // 4x4 warp grid
    const int m0 = blockIdx.y * 256, n0 = blockIdx.x * 128;

    const float* X = g_X + (PROJ ? (size_t)z * OUT_ELEMS : 0);
    const float* W = g_W + (size_t)z * HD * HD;
    const float* bias = PROJ ? ((z == 0) ? b0 : (z == 1) ? b1 : b2) : b0;

    float acc[16][4];
#pragma unroll
    for (int i = 0; i < 16; i++)
#pragma unroll
        for (int j = 0; j < 4; j++) acc[i][j] = 0.f;

    auto cp_stage = [&](int st, int k0) {
        uint32_t d = sb + st * GSTG;
#pragma unroll
        for (int t = 0; t < 4; ++t) {               // A: 2048 granules
            int i = tid + t * 512;
            int r = i >> 3, c = i & 7;
            CP16(d + r*GSTRB + c*16, X + (size_t)(m0 + r)*HD + k0 + c*4);
        }
#pragma unroll
        for (int t = 0; t < 2; ++t) {               // B: 1024 granules
            int i = tid + t * 512;
            int r = i >> 3, c = i & 7;
            CP16(d + GA_BYTES + r*GSTRB + c*16, W + (size_t)(n0 + r)*HD + k0 + c*4);
        }
        CP_COMMIT();
    };

    const int mrow = (lane & 7) | ((lane & 16) >> 1);   // 0..15
    const int mcol = (lane & 8) ? 16 : 0;               // byte offset

    cp_stage(0, 0);
    cp_stage(1, 32);

    int s = 0;
#pragma unroll 1
    for (int c = 0; c < 32; ++c) {
        if (c < 31) { CP_WAIT1(); } else { CP_WAIT0(); }
        __syncthreads();
        if (c + 2 < 32) cp_stage((s + 2) % 3, (c + 2) * 32);

        const uint32_t stA = sb + s * GSTG;
        const uint32_t stB = stA + GA_BYTES;
#pragma unroll
        for (int ks = 0; ks < 4; ++ks) {
            uint32_t a[4][4], b[2][4];
#pragma unroll
            for (int fm = 0; fm < 4; ++fm)
                ldmx4(a[fm], stA + (wm*64 + fm*16 + mrow)*GSTRB + ks*32 + mcol);
#pragma unroll
            for (int gp = 0; gp < 2; ++gp)
                ldmx4(b[gp], stB + (wn*32 + gp*16 + mrow)*GSTRB + ks*32 + mcol);
#pragma unroll
            for (int fm = 0; fm < 4; ++fm)
#pragma unroll
                for (int g = 0; g < 4; ++g) {
                    const int gp = g >> 1, sel = (g & 1) * 2;
                    mma_tf32(acc[fm*4 + g], a[fm][0], a[fm][2], a[fm][1], a[fm][3],
                             b[gp][sel], b[gp][sel + 1]);
                }
        }
        s = (s + 1) % 3;
    }

    // epilogue
#pragma unroll
    for (int fm = 0; fm < 4; ++fm)
#pragma unroll
        for (int fn = 0; fn < 4; ++fn) {
            const float* cc = acc[fm*4 + fn];
            const int m = m0 + wm*64 + fm*16 + (lane >> 2);
            const int n = n0 + wn*32 + fn*8 + (lane & 3)*2;
            float2 bv = *(const float2*)&bias[n];
            float v0 = cc[0] + bv.x, v1 = cc[1] + bv.y;    // row m
            float v2 = cc[2] + bv.x, v3 = cc[3] + bv.y;    // row m+8
            if (!PROJ) {
                *(float2*)&outp[(size_t)m * HD + n]       = make_float2(v0, v1);
                *(float2*)&outp[(size_t)(m + 8) * HD + n] = make_float2(v2, v3);
            } else {
                const int b = m >> 10, sq = m & 1023;
                const int h = n >> 6,  d  = n & 63;
                if (z == 2) {
                    uint32_t* VTd = (uint32_t*)g_VT;
                    size_t vb = ((size_t)(b*HH + h)) * HDK * HS;
                    VTd[vb + (size_t)d*HS + sq]           = cvt_tf32(v0);
                    VTd[vb + (size_t)(d+1)*HS + sq]       = cvt_tf32(v1);
                    VTd[vb + (size_t)d*HS + sq + 8]       = cvt_tf32(v2);
                    VTd[vb + (size_t)(d+1)*HS + sq + 8]   = cvt_tf32(v3);
                } else {
                    float sc = (z == 0) ? 0.125f : 1.0f;
                    float* Y = (z == 0) ? g_Q : g_K;
                    size_t rbase = (((size_t)(b*HH + h))*HS + sq) * HDK;
                    uint2 u0 = make_uint2(cvt_tf32(v0 * sc), cvt_tf32(v1 * sc));
                    uint2 u1 = make_uint2(cvt_tf32(v2 * sc), cvt_tf32(v3 * sc));
                    *(uint2*)&Y[rbase + d]         = u0;
                    *(uint2*)&Y[rbase + 8*HDK + d] = u1;
                }
            }
        }
}

// ---------------------------------------------------------------------------
// Warp-specialized fused attention (tf32, 512 threads):
// warps 0-7 (producer): per 64-key chunk, QK^T -> exp -> sP + row sums.
// warps 8-15 (consumer): P@V on chunk c-1 CONCURRENTLY (raw exp P, inv in
// epilogue). Lockstep 1-sync-per-chunk pipeline, 16 chunks. K and VT each
// 2-stage cp.async (independent per-warp-group wait counters).
// CTA = (32 q rows, bh).
// ---------------------------------------------------------------------------
#define SPSTR 1028                      // floats per sP row (≡ 4 mod 32)
#define SPB (32*SPSTR*4)                // 131584
#define OFF_Q SPB                       // 131584
#define QSTRB 272                       // 64 floats + 16B pad
#define OFF_K (OFF_Q + 32*QSTRB)        // 140288
#define KSTGB (64*QSTRB)                // 17408 per 64-key stage
#define OFF_VT (OFF_K + 2*KSTGB)        // 175104
#define VSTGB (64*QSTRB)                // 17408 per stage
#define OFF_RED (OFF_VT + 2*VSTGB)      // 209920 (32 rows x 4 wn x float)
#define OFF_STATS (OFF_RED + 512)       // 210432 (32 x inv)
#define OFF_CTXRED OFF_K                // reuse K region (dead) for ctx dump
#define ATTN_SMEM (OFF_STATS + 128)     // 210560

__global__ __launch_bounds__(512, 1)
void attn_fused(float* __restrict__ attn_out)
{
    extern __shared__ char sm[];
    const uint32_t sb = smem_u32(sm);
    float* sP = (float*)sm;

    const int tid = threadIdx.x;
    const int wid = tid >> 5, lane = tid & 31;
    const int bh = blockIdx.y;
    const int q0 = blockIdx.x * 32;
    const int mrow = (lane & 7) | ((lane & 16) >> 1);
    const int mcol = (lane & 8) ? 16 : 0;
    const bool producer = (wid < 8);

    const float* Qg  = g_Q  + (size_t)bh * HS * HDK;
    const float* Kg  = g_K  + (size_t)bh * HS * HDK;
    const float* VTg = g_VT + (size_t)bh * HDK * HS;

    // Q tile 32x64 (1 granule/thread over 512 threads)
    {
        int r = tid >> 4, c = tid & 15;
        *(uint4*)(sm + OFF_Q + r*QSTRB + c*16) =
            *(const uint4*)(Qg + (size_t)(q0 + r)*HDK + c*4);
    }

    // chunk = 64 keys; producer threads 0-255, consumer threads 256-511
    auto cp_K = [&](int st, int ck) {      // producer: 1024 granules, 4/thread
        uint32_t d = sb + OFF_K + st * KSTGB;
#pragma unroll
        for (int t = 0; t < 4; ++t) {
            int i = tid + t * 256;         // tid in 0..255
            int r = i >> 4, c = i & 15;
            CP16(d + r*QSTRB + c*16, Kg + (size_t)(ck*64 + r)*HDK + c*4);
        }
        CP_COMMIT();
    };
    auto cp_VT = [&](int st, int ck) {     // consumer: 1024 granules, 4/thread
        uint32_t d = sb + OFF_VT + st * VSTGB;
        int ctid = tid - 256;
#pragma unroll
        for (int t = 0; t < 4; ++t) {
            int i = ctid + t * 256;
            int r = i >> 4, c = i & 15;    // r = d row, c*4 = key within chunk
            CP16(d + r*QSTRB + c*16, VTg + (size_t)r*HS + ck*64 + c*4);
        }
        CP_COMMIT();
    };

    if (producer) cp_K(0, 0);
    else          cp_VT(0, 0);
    __syncthreads();                        // Q visible

    // producer decomposition: wm = 16 q rows, wn = 16-key group
    const int wm = wid & 1, wn = (wid >> 1) & 3;
    uint32_t qf[8][4];
    if (producer) {
#pragma unroll
        for (int ks = 0; ks < 8; ++ks)
            ldmx4(qf[ks], sb + OFF_Q + (wm*16 + mrow)*QSTRB + ks*32 + mcol);
    }
    float s_a = 0.f, s_b = 0.f;             // producer row sums

    // consumer decomposition: kq = k-half, wmp = 16 q rows, wnp = 32-d group
    const int kq = (wid >> 2) & 1, wmp = wid & 1, wnp = (wid >> 1) & 1;
    float acc2[4][4];
#pragma unroll
    for (int i = 0; i < 4; i++)
#pragma unroll
        for (int j = 0; j < 4; j++) acc2[i][j] = 0.f;

    // ---- lockstep pipeline: 17 iterations over 16 chunks ----
#pragma unroll 1
    for (int c = 0; c <= 16; ++c) {
        CP_WAIT0();                          // own group's cps complete
        __syncthreads();                     // K(c)/VT(c-1)/sP(c-1) visible

        if (producer) {
            if (c < 15) cp_K((c + 1) & 1, c + 1);   // overlaps compute
            if (c < 16) {
                const uint32_t stK = sb + OFF_K + (c & 1) * KSTGB;
                float acc[2][4];
#pragma unroll
                for (int i = 0; i < 2; i++)
#pragma unroll
                    for (int j = 0; j < 4; j++) acc[i][j] = 0.f;
#pragma unroll
                for (int ks = 0; ks < 8; ++ks) {
                    uint32_t b[4];
                    ldmx4(b, stK + (wn*16 + mrow)*QSTRB + ks*32 + mcol);
#pragma unroll
                    for (int g = 0; g < 2; ++g)
                        mma_tf32(acc[g], qf[ks][0], qf[ks][2], qf[ks][1],
                                 qf[ks][3], b[g*2], b[g*2+1]);
                }
                int row = wm*16 + (lane >> 2);
                int col = c*64 + wn*16 + (lane & 3)*2;
#pragma unroll
                for (int g = 0; g < 2; ++g) {
                    float e0 = __expf(acc[g][0]), e1 = __expf(acc[g][1]);
                    float e2 = __expf(acc[g][2]), e3 = __expf(acc[g][3]);
                    s_a += e0 + e1;
                    s_b += e2 + e3;
                    *(float2*)&sP[(size_t)row * SPSTR + col + g*8]       = make_float2(e0, e1);
                    *(float2*)&sP[(size_t)(row + 8) * SPSTR + col + g*8] = make_float2(e2, e3);
                }
            } else {
                // c == 16: reduce sums while consumer finishes chunk 15
#pragma unroll
                for (int o = 1; o <= 2; o <<= 1) {
                    s_a += __shfl_xor_sync(0xffffffffu, s_a, o);
                    s_b += __shfl_xor_sync(0xffffffffu, s_b, o);
                }
                if ((lane & 3) == 0) {
                    int r = wm*16 + (lane >> 2);
                    *(float*)(sm + OFF_RED + ((size_t)r*4 + wn)*4)     = s_a;
                    *(float*)(sm + OFF_RED + ((size_t)(r+8)*4 + wn)*4) = s_b;
                }
                BAR_PROD();                  // producer-only barrier
                if (tid < 32) {
                    float s = 0.f;
#pragma unroll
                    for (int w = 0; w < 4; ++w)
                        s += *(float*)(sm + OFF_RED + ((size_t)tid*4 + w)*4);
                    *(float*)(sm + OFF_STATS + tid*4) = 1.f / s;
                }
            }
        } else {
            if (c >= 1 && c < 16) cp_VT(c & 1, c);   // overlaps compute
            if (c >= 1) {
                const int ck = c - 1;
                const uint32_t stVT = sb + OFF_VT + (ck & 1) * VSTGB;
#pragma unroll
                for (int ks2 = 0; ks2 < 4; ++ks2) {
                    const int ks = kq*4 + ks2;        // k8 index within chunk
                    uint32_t a[4], b[2][4];
                    // raw fp32 exp values; HW truncates to tf32
                    ldmx4(a, sb + (wmp*16 + mrow)*(SPSTR*4) + (ck*64 + ks*8)*4 + mcol);
#pragma unroll
                    for (int gp = 0; gp < 2; ++gp)
                        ldmx4(b[gp], stVT + (wnp*32 + gp*16 + mrow)*QSTRB + ks*32 + mcol);
#pragma unroll
                    for (int g = 0; g < 4; ++g) {
                        const int gp = g >> 1, sel = (g & 1) * 2;
                        mma_tf32(acc2[g], a[0], a[2], a[1], a[3],
                                 b[gp][sel], b[gp][sel+1]);
                    }
                }
            }
        }
    }
    __syncthreads();                         // inv + all sP + ctx accs ready

    // consumer kq==1 warps dump ctx partials (K region dead)
    if (!producer && kq == 1) {
        const int grp = wmp*2 + wnp;
        float* d = (float*)(sm + OFF_CTXRED) + ((size_t)grp*32 + lane)*16;
#pragma unroll
        for (int f = 0; f < 4; ++f)
            *(float4*)(d + f*4) = make_float4(acc2[f][0], acc2[f][1],
                                              acc2[f][2], acc2[f][3]);
    }
    __syncthreads();

    // attn gmem write: all 512 threads, coalesced float4 (sP * inv)
    {
        float* abase = attn_out + ((size_t)bh * HS + q0) * HS;
#pragma unroll
        for (int i = 0; i < 16; ++i) {
            int p = tid + i*512;
            int row = p >> 8, c4 = p & 255;
            float inv = *(float*)(sm + OFF_STATS + row*4);
            float4 v = *(const float4*)&sP[(size_t)row * SPSTR + c4*4];
            v.x *= inv; v.y *= inv; v.z *= inv; v.w *= inv;
            __stcs((float4*)(abase + (size_t)row*HS + c4*4), v);
        }
    }

    // consumer kq==0 warps: add partials, scale by inv, store ctx
    if (!producer && kq == 0) {
        const int grp = wmp*2 + wnp;
        const float* d = (const float*)(sm + OFF_CTXRED) + ((size_t)grp*32 + lane)*16;
#pragma unroll
        for (int f = 0; f < 4; ++f) {
            float4 p = *(const float4*)(d + f*4);
            acc2[f][0] += p.x; acc2[f][1] += p.y;
            acc2[f][2] += p.z; acc2[f][3] += p.w;
        }
        const int b = bh >> 4, h = bh & 15;
        float inv0 = *(float*)(sm + OFF_STATS + (wmp*16 + (lane >> 2))*4);
        float inv1 = *(float*)(sm + OFF_STATS + (wmp*16 + (lane >> 2) + 8)*4);
#pragma unroll
        for (int fn = 0; fn < 4; ++fn) {
            int s  = q0 + wmp*16 + (lane >> 2);
            int cl = h*64 + wnp*32 + fn*8 + (lane & 3)*2;
            size_t o0 = (size_t)(b*HS + s)     * HD + cl;
            size_t o1 = (size_t)(b*HS + s + 8) * HD + cl;
            *(uint2*)&g_X[o0] = make_uint2(cvt_tf32(acc2[fn][0] * inv0),
                                           cvt_tf32(acc2[fn][1] * inv0));
            *(uint2*)&g_X[o1] = make_uint2(cvt_tf32(acc2[fn][2] * inv1),
                                           cvt_tf32(acc2[fn][3] * inv1));
        }
    }
}

// ---------------------------------------------------------------------------
extern "C" void kernel_launch(void* const* d_in, const int* in_sizes, int n_in,
                              void* d_out, int out_size)
{
    const float* q  = (const float*)d_in[0];
    const float* k  = (const float*)d_in[1];
    const float* v  = (const float*)d_in[2];
    const float* Wq = (const float*)d_in[3];
    const float* bq = (const float*)d_in[4];
    const float* Wk = (const float*)d_in[5];
    const float* bk = (const float*)d_in[6];
    const float* Wv = (const float*)d_in[7];
    const float* bv = (const float*)d_in[8];
    const float* Wo = (const float*)d_in[9];
    const float* bo = (const float*)d_in[10];

    float* out  = (float*)d_out;
    float* attn = out + OUT_ELEMS;

    cudaFuncSetAttribute(gemm5<true>,  cudaFuncAttributeMaxDynamicSharedMemorySize, GT_SMEM);
    cudaFuncSetAttribute(gemm5<false>, cudaFuncAttributeMaxDynamicSharedMemorySize, GT_SMEM);
    cudaFuncSetAttribute(attn_fused, cudaFuncAttributeMaxDynamicSharedMemorySize, ATTN_SMEM);

    // 1. cvt q,k,v -> g_X
    repackQKV_k<<<3 * N4 / 256, 256>>>((const float4*)q, (const float4*)k,
                                       (const float4*)v);
    // 2. transpose+cvt all 4 weights
    wT4_k<<<dim3(HD/32, HD/32, 4), dim3(32, 8)>>>(Wq, Wk, Wv, Wo);
    // 3. Q,K,V projections (V writes g_VT transposed directly)
    gemm5<true><<<dim3(HD/128, MTOT/256, 3), 512, GT_SMEM>>>(bq, bk, bv, nullptr);
    // 4. warp-specialized fused attention
    attn_fused<<<dim3(HS/32, NBH), 512, ATTN_SMEM>>>(attn);
    // 5. out = ctx @ Wo + bo
    gemm5<false><<<dim3(HD/128, MTOT/256), 512, GT_SMEM>>>(bo, nullptr, nullptr, out);
}